// round 1
// baseline (speedup 1.0000x reference)
#include <cuda_runtime.h>
#include <math.h>

#define Bn 32
#define Cn 512
#define HWn 3136
#define NV4 784          // HWn / 4
#define Kk 3
#define PADk 1
#define NROWS (Bn * Cn)  // 16384

__device__ float g_y[NROWS];
__device__ float g_attn[NROWS];

// ---------------------------------------------------------------------------
// Kernel 1: y[b,c] = mean over HW. One warp per (b,c) row, float4 loads.
// ---------------------------------------------------------------------------
__global__ void mean_kernel(const float* __restrict__ x) {
    int warp = (blockIdx.x * blockDim.x + threadIdx.x) >> 5;
    int lane = threadIdx.x & 31;
    if (warp >= NROWS) return;
    const float4* row = (const float4*)(x + (size_t)warp * HWn);
    float s = 0.0f;
    #pragma unroll 4
    for (int i = lane; i < NV4; i += 32) {
        float4 v = row[i];
        s += (v.x + v.y) + (v.z + v.w);
    }
    #pragma unroll
    for (int o = 16; o > 0; o >>= 1)
        s += __shfl_down_sync(0xffffffffu, s, o);
    if (lane == 0) g_y[warp] = s * (1.0f / (float)HWn);
}

// ---------------------------------------------------------------------------
// Kernel 2: deformable channel conv + sigmoid -> g_attn[b, c].
// One block per batch (32 blocks), one thread per channel position (512).
// ---------------------------------------------------------------------------
__global__ void attn_kernel(const float* __restrict__ w_offset,
                            const float* __restrict__ w_deform,
                            const float* __restrict__ b_deform) {
    __shared__ float sy[Cn];
    int b = blockIdx.x;
    int p = threadIdx.x;       // 0..511
    sy[p] = g_y[b * Cn + p];
    __syncthreads();

    // tiny weights: read-through (L1/const cached)
    float wo[Kk][Kk];
    #pragma unroll
    for (int k = 0; k < Kk; k++)
        #pragma unroll
        for (int j = 0; j < Kk; j++)
            wo[k][j] = w_offset[k * Kk + j];
    float wd0 = w_deform[0], wd1 = w_deform[1], wd2 = w_deform[2];
    float acc = b_deform[0];

    float wd[Kk] = {wd0, wd1, wd2};
    #pragma unroll
    for (int k = 0; k < Kk; k++) {
        // offset[b,k,p] = sum_j w_offset[k,0,j] * ypad[p + j - PAD]
        float off = 0.0f;
        #pragma unroll
        for (int j = 0; j < Kk; j++) {
            int ii = p + j - PADk;
            float yv = (ii >= 0 && ii < Cn) ? sy[ii] : 0.0f;
            off = fmaf(wo[k][j], yv, off);
        }
        float pos = (float)(p + k - PADk) + off;
        float p0 = floorf(pos);
        float frac = pos - p0;
        int p0i = (int)p0;
        float v0 = (p0i >= 0 && p0i < Cn) ? sy[p0i] : 0.0f;
        int p1i = p0i + 1;
        float v1 = (p1i >= 0 && p1i < Cn) ? sy[p1i] : 0.0f;
        float v = fmaf(v1 - v0, frac, v0);   // v0*(1-frac) + v1*frac
        acc = fmaf(wd[k], v, acc);
    }
    g_attn[b * Cn + p] = 1.0f / (1.0f + __expf(-acc));
}

// ---------------------------------------------------------------------------
// Kernel 3: out[b,c,h,w] = attn[b,c] * x[b,c,h,w]. One block per row.
// ---------------------------------------------------------------------------
__global__ void scale_kernel(const float* __restrict__ x,
                             float* __restrict__ out) {
    int row = blockIdx.x;
    float a = g_attn[row];
    const float4* xin = (const float4*)(x + (size_t)row * HWn);
    float4* o = (float4*)(out + (size_t)row * HWn);
    #pragma unroll 2
    for (int i = threadIdx.x; i < NV4; i += blockDim.x) {
        float4 v = xin[i];
        v.x *= a; v.y *= a; v.z *= a; v.w *= a;
        o[i] = v;
    }
}

extern "C" void kernel_launch(void* const* d_in, const int* in_sizes, int n_in,
                              void* d_out, int out_size) {
    const float* x        = (const float*)d_in[0];
    const float* w_offset = (const float*)d_in[1];
    const float* w_deform = (const float*)d_in[2];
    const float* b_deform = (const float*)d_in[3];
    float* out = (float*)d_out;

    // 1: mean -> g_y.  8 warps/block -> 2048 blocks for 16384 rows.
    mean_kernel<<<NROWS / 8, 256>>>(x);
    // 2: attention scalar per (b,c)
    attn_kernel<<<Bn, Cn>>>(w_offset, w_deform, b_deform);
    // 3: elementwise scale
    scale_kernel<<<NROWS, 256>>>(x, out);
}

// round 2
// speedup vs baseline: 1.0888x; 1.0888x over previous
#include <cuda_runtime.h>
#include <math.h>

#define Bn 32
#define Cn 512
#define HWn 3136
#define NV4 784          // HWn / 4
#define Kk 3
#define PADk 1
#define NROWS (Bn * Cn)  // 16384

// Rows below this threshold are read with evict-first (streaming) hint in the
// mean pass: they cannot survive in L2 anyway (x tail ~> L2 capacity), so
// don't let them evict the tail rows we want resident for the scale pass.
// L2 ~126 MB, row = 3136*4 = 12.544 KB -> ~10000 rows fit; keep margin.
#define STREAM_THRESH 7680

__device__ float g_y[NROWS];
__device__ float g_attn[NROWS];

// ---------------------------------------------------------------------------
// Kernel 1: y[b,c] = mean over HW. One warp per (b,c) row, float4 loads.
// Early rows: __ldcs (evict-first). Tail rows: default (stay in L2).
// ---------------------------------------------------------------------------
__global__ void mean_kernel(const float* __restrict__ x) {
    int warp = (blockIdx.x * blockDim.x + threadIdx.x) >> 5;
    int lane = threadIdx.x & 31;
    if (warp >= NROWS) return;
    const float4* row = (const float4*)(x + (size_t)warp * HWn);
    float s = 0.0f;
    if (warp < STREAM_THRESH) {
        #pragma unroll 4
        for (int i = lane; i < NV4; i += 32) {
            float4 v = __ldcs(&row[i]);
            s += (v.x + v.y) + (v.z + v.w);
        }
    } else {
        #pragma unroll 4
        for (int i = lane; i < NV4; i += 32) {
            float4 v = __ldg(&row[i]);
            s += (v.x + v.y) + (v.z + v.w);
        }
    }
    #pragma unroll
    for (int o = 16; o > 0; o >>= 1)
        s += __shfl_down_sync(0xffffffffu, s, o);
    if (lane == 0) g_y[warp] = s * (1.0f / (float)HWn);
}

// ---------------------------------------------------------------------------
// Kernel 2: deformable channel conv + sigmoid -> g_attn[b, c].
// One block per batch (32 blocks), one thread per channel position (512).
// ---------------------------------------------------------------------------
__global__ void attn_kernel(const float* __restrict__ w_offset,
                            const float* __restrict__ w_deform,
                            const float* __restrict__ b_deform) {
    __shared__ float sy[Cn];
    int b = blockIdx.x;
    int p = threadIdx.x;       // 0..511
    sy[p] = g_y[b * Cn + p];
    __syncthreads();

    float wo[Kk][Kk];
    #pragma unroll
    for (int k = 0; k < Kk; k++)
        #pragma unroll
        for (int j = 0; j < Kk; j++)
            wo[k][j] = w_offset[k * Kk + j];
    float wd[Kk] = {w_deform[0], w_deform[1], w_deform[2]};
    float acc = b_deform[0];

    #pragma unroll
    for (int k = 0; k < Kk; k++) {
        float off = 0.0f;
        #pragma unroll
        for (int j = 0; j < Kk; j++) {
            int ii = p + j - PADk;
            float yv = (ii >= 0 && ii < Cn) ? sy[ii] : 0.0f;
            off = fmaf(wo[k][j], yv, off);
        }
        float pos = (float)(p + k - PADk) + off;
        float p0 = floorf(pos);
        float frac = pos - p0;
        int p0i = (int)p0;
        float v0 = (p0i >= 0 && p0i < Cn) ? sy[p0i] : 0.0f;
        int p1i = p0i + 1;
        float v1 = (p1i >= 0 && p1i < Cn) ? sy[p1i] : 0.0f;
        float v = fmaf(v1 - v0, frac, v0);
        acc = fmaf(wd[k], v, acc);
    }
    g_attn[b * Cn + p] = 1.0f / (1.0f + __expf(-acc));
}

// ---------------------------------------------------------------------------
// Kernel 3: out = attn * x, processed in REVERSE row order so the first rows
// touched are the x-tail still resident in L2 from the mean pass.
// Streaming stores keep the output from evicting x.
// ---------------------------------------------------------------------------
__global__ void scale_kernel(const float* __restrict__ x,
                             float* __restrict__ out) {
    int row = (NROWS - 1) - blockIdx.x;     // reverse order
    float a = g_attn[row];
    const float4* xin = (const float4*)(x + (size_t)row * HWn);
    float4* o = (float4*)(out + (size_t)row * HWn);
    #pragma unroll 2
    for (int i = threadIdx.x; i < NV4; i += blockDim.x) {
        float4 v = __ldg(&xin[i]);
        v.x *= a; v.y *= a; v.z *= a; v.w *= a;
        __stcs(&o[i], v);
    }
}

extern "C" void kernel_launch(void* const* d_in, const int* in_sizes, int n_in,
                              void* d_out, int out_size) {
    const float* x        = (const float*)d_in[0];
    const float* w_offset = (const float*)d_in[1];
    const float* w_deform = (const float*)d_in[2];
    const float* b_deform = (const float*)d_in[3];
    float* out = (float*)d_out;

    mean_kernel<<<NROWS / 8, 256>>>(x);
    attn_kernel<<<Bn, Cn>>>(w_offset, w_deform, b_deform);
    scale_kernel<<<NROWS, 256>>>(x, out);
}

// round 3
// speedup vs baseline: 1.1084x; 1.0180x over previous
#include <cuda_runtime.h>
#include <math.h>

#define Bn 32
#define Cn 512
#define HWn 3136
#define NV4 784             // HWn / 4
#define NROWS (Bn * Cn)     // 16384
#define BPC 8               // batches per chunk
#define NCHUNK 4
#define RPC (BPC * Cn)      // 4096 rows per chunk
#define MEAN_BLOCKS (RPC / 8)  // 512: each mean block = 8 rows, warp per row

__device__ float g_y[NROWS];

// ---------------------------------------------------------------------------
// Fused pipeline stage.
//   mean_chunk  >= 0 : some blocks compute row means of that chunk (DRAM read,
//                      normal policy -> lines retained in L2 for next stage)
//   scale_chunk >= 0 : some blocks scale rows of that chunk (reads are L2-hot
//                      from the previous stage; evict-first reads + writes)
// Mixed grids interleave 8 scale blocks : 1 mean block (balanced DRAM bytes:
// mean block reads 100KB DRAM, 8 scale blocks write 100KB DRAM).
// ---------------------------------------------------------------------------
__global__ void fused_kernel(const float* __restrict__ x,
                             float* __restrict__ out,
                             const float* __restrict__ w_offset,
                             const float* __restrict__ w_deform,
                             const float* __restrict__ b_deform,
                             int mean_chunk, int scale_chunk) {
    int bid = blockIdx.x;
    bool do_mean;
    int mean_blk = 0, scale_row = 0;
    if (mean_chunk >= 0 && scale_chunk >= 0) {
        int g = bid / 9, pos = bid - g * 9;
        if (pos == 8) { do_mean = true;  mean_blk  = g; }
        else          { do_mean = false; scale_row = scale_chunk * RPC + g * 8 + pos; }
    } else if (mean_chunk >= 0) {
        do_mean = true;  mean_blk = bid;
    } else {
        do_mean = false; scale_row = scale_chunk * RPC + bid;
    }

    if (do_mean) {
        // 8 rows per block, one warp per row (24 independent loads/lane -> MLP)
        int warp = threadIdx.x >> 5, lane = threadIdx.x & 31;
        int row = mean_chunk * RPC + mean_blk * 8 + warp;
        const float4* rp = (const float4*)(x + (size_t)row * HWn);
        float s = 0.0f;
        #pragma unroll 4
        for (int i = lane; i < NV4; i += 32) {
            float4 v = __ldg(&rp[i]);          // normal policy: retain in L2
            s += (v.x + v.y) + (v.z + v.w);
        }
        #pragma unroll
        for (int o = 16; o > 0; o >>= 1)
            s += __shfl_down_sync(0xffffffffu, s, o);
        if (lane == 0) g_y[row] = s * (1.0f / (float)HWn);
        return;
    }

    // ---- scale block: compute attn for this row inline, then stream ----
    __shared__ float sa;
    if (threadIdx.x == 0) {
        int b = scale_row / Cn;
        int p = scale_row - b * Cn;
        const float* yb = g_y + b * Cn;
        float acc = b_deform[0];
        #pragma unroll
        for (int k = 0; k < 3; k++) {
            // offset[b,k,p] = sum_j w_offset[k,0,j] * ypad[p + j - 1]
            float off = 0.0f;
            #pragma unroll
            for (int j = 0; j < 3; j++) {
                int ii = p + j - 1;
                float yv = (ii >= 0 && ii < Cn) ? yb[ii] : 0.0f;
                off = fmaf(w_offset[k * 3 + j], yv, off);
            }
            float pos = (float)(p + k - 1) + off;
            float p0 = floorf(pos);
            float frac = pos - p0;
            int p0i = (int)p0;
            float v0 = (p0i >= 0     && p0i < Cn)     ? yb[p0i]     : 0.0f;
            float v1 = (p0i + 1 >= 0 && p0i + 1 < Cn) ? yb[p0i + 1] : 0.0f;
            acc = fmaf(w_deform[k], fmaf(v1 - v0, frac, v0), acc);
        }
        sa = 1.0f / (1.0f + __expf(-acc));
    }
    __syncthreads();
    float a = sa;

    const float4* xin = (const float4*)(x + (size_t)scale_row * HWn);
    float4* o = (float4*)(out + (size_t)scale_row * HWn);
    #pragma unroll 2
    for (int i = threadIdx.x; i < NV4; i += 256) {
        float4 v = __ldcs(&xin[i]);            // dead after this: evict-first
        v.x *= a; v.y *= a; v.z *= a; v.w *= a;
        __stcs(&o[i], v);                      // don't evict retained chunk
    }
}

extern "C" void kernel_launch(void* const* d_in, const int* in_sizes, int n_in,
                              void* d_out, int out_size) {
    const float* x        = (const float*)d_in[0];
    const float* w_offset = (const float*)d_in[1];
    const float* w_deform = (const float*)d_in[2];
    const float* b_deform = (const float*)d_in[3];
    float* out = (float*)d_out;

    // Software pipeline over 4 chunks of 8 batches:
    //   K0: mean(c0)
    //   K1: mean(c1) || scale(c0)   ... overlapped DRAM read + write
    //   K2: mean(c2) || scale(c1)
    //   K3: mean(c3) || scale(c2)
    //   K4: scale(c3)
    fused_kernel<<<MEAN_BLOCKS, 256>>>(x, out, w_offset, w_deform, b_deform, 0, -1);
    fused_kernel<<<RPC + MEAN_BLOCKS, 256>>>(x, out, w_offset, w_deform, b_deform, 1, 0);
    fused_kernel<<<RPC + MEAN_BLOCKS, 256>>>(x, out, w_offset, w_deform, b_deform, 2, 1);
    fused_kernel<<<RPC + MEAN_BLOCKS, 256>>>(x, out, w_offset, w_deform, b_deform, 3, 2);
    fused_kernel<<<RPC, 256>>>(x, out, w_offset, w_deform, b_deform, -1, 3);
}